// round 1
// baseline (speedup 1.0000x reference)
#include <cuda_runtime.h>
#include <math.h>

#define NB 8192
#define ND 128
#define C_ALPHA 2.0f
#define C_BETA 50.0f
#define C_BASE 0.5f
#define C_MARGIN 0.1f

// 256 MB scratch for the similarity matrix + per-row outputs.
__device__ float g_sim[(size_t)NB * NB];
__device__ float g_row_loss[NB];
__device__ int   g_valid[NB];

// ---------------------------------------------------------------------------
// Kernel 1: sim = E * E^T  (fp32, 128x128 block tile, full K=128 in SMEM)
// ---------------------------------------------------------------------------
#define BM 128
#define BN 128

__global__ __launch_bounds__(256) void gemm_kernel(const float* __restrict__ E) {
    extern __shared__ float sm[];
    float* As = sm;               // [ND][BM]  k-major
    float* Bs = sm + ND * BM;     // [ND][BN]  k-major

    const int tid = threadIdx.x;
    const int bm = blockIdx.y * BM;
    const int bn = blockIdx.x * BN;

    // Load A and B tiles (transpose to k-major). Each tile: 128 rows x 128 k.
    // 128 * 32 float4 = 4096 float4 per tile; 16 per thread per tile.
    for (int t = tid; t < BM * (ND / 4); t += 256) {
        const int r  = t >> 5;        // row within tile (0..127)
        const int c4 = t & 31;        // float4 index within row (0..31)
        float4 va = ((const float4*)E)[(size_t)(bm + r) * (ND / 4) + c4];
        As[(c4 * 4 + 0) * BM + r] = va.x;
        As[(c4 * 4 + 1) * BM + r] = va.y;
        As[(c4 * 4 + 2) * BM + r] = va.z;
        As[(c4 * 4 + 3) * BM + r] = va.w;
        float4 vb = ((const float4*)E)[(size_t)(bn + r) * (ND / 4) + c4];
        Bs[(c4 * 4 + 0) * BN + r] = vb.x;
        Bs[(c4 * 4 + 1) * BN + r] = vb.y;
        Bs[(c4 * 4 + 2) * BN + r] = vb.z;
        Bs[(c4 * 4 + 3) * BN + r] = vb.w;
    }
    __syncthreads();

    const int tx = tid & 15;   // n direction
    const int ty = tid >> 4;   // m direction

    float acc[8][8];
#pragma unroll
    for (int i = 0; i < 8; i++)
#pragma unroll
        for (int j = 0; j < 8; j++) acc[i][j] = 0.0f;

#pragma unroll 4
    for (int k = 0; k < ND; k++) {
        float4 a0 = *(const float4*)(As + k * BM + ty * 8);
        float4 a1 = *(const float4*)(As + k * BM + ty * 8 + 4);
        float4 b0 = *(const float4*)(Bs + k * BN + tx * 8);
        float4 b1 = *(const float4*)(Bs + k * BN + tx * 8 + 4);
        float a[8] = {a0.x, a0.y, a0.z, a0.w, a1.x, a1.y, a1.z, a1.w};
        float b[8] = {b0.x, b0.y, b0.z, b0.w, b1.x, b1.y, b1.z, b1.w};
#pragma unroll
        for (int i = 0; i < 8; i++)
#pragma unroll
            for (int j = 0; j < 8; j++) acc[i][j] += a[i] * b[j];
    }

#pragma unroll
    for (int i = 0; i < 8; i++) {
        size_t row = (size_t)(bm + ty * 8 + i);
        float4* dst = (float4*)(g_sim + row * NB + bn + tx * 8);
        dst[0] = make_float4(acc[i][0], acc[i][1], acc[i][2], acc[i][3]);
        dst[1] = make_float4(acc[i][4], acc[i][5], acc[i][6], acc[i][7]);
    }
}

// ---------------------------------------------------------------------------
// Kernel 2: per-row mining + loss. One CTA per row; row staged in SMEM so
// both passes (extrema, then exp sums) read HBM only once.
// ---------------------------------------------------------------------------
__global__ __launch_bounds__(256) void row_kernel(const int* __restrict__ labels) {
    extern __shared__ float sm[];
    float* srow = sm;                     // NB floats  (32 KB)
    int*   slab = (int*)(sm + NB);        // NB ints    (32 KB)
    __shared__ float rf[256];
    __shared__ int   ri[256];
    __shared__ float s_pmin, s_nmax;

    const int i   = blockIdx.x;
    const int tid = threadIdx.x;

    for (int t = tid; t < NB / 4; t += 256) {
        ((float4*)srow)[t] = ((const float4*)(g_sim + (size_t)i * NB))[t];
        ((int4*)slab)[t]   = ((const int4*)labels)[t];
    }
    __syncthreads();

    const int li = slab[i];

    // Pass 1: pos_min (same-class, j!=i), neg_max (diff-class)
    float pmin = INFINITY, nmax = -INFINITY;
    for (int j = tid; j < NB; j += 256) {
        float s = srow[j];
        bool same = (slab[j] == li);
        if (same && j != i) pmin = fminf(pmin, s);
        if (!same)          nmax = fmaxf(nmax, s);
    }
    rf[tid] = pmin; __syncthreads();
    for (int o = 128; o > 0; o >>= 1) {
        if (tid < o) rf[tid] = fminf(rf[tid], rf[tid + o]);
        __syncthreads();
    }
    if (tid == 0) s_pmin = rf[0];
    __syncthreads();
    rf[tid] = nmax; __syncthreads();
    for (int o = 128; o > 0; o >>= 1) {
        if (tid < o) rf[tid] = fmaxf(rf[tid], rf[tid + o]);
        __syncthreads();
    }
    if (tid == 0) s_nmax = rf[0];
    __syncthreads();
    pmin = s_pmin;
    nmax = s_nmax;

    // Pass 2: hard-pair sums + existence flags (bit0 anyp, bit1 anyn, bit2 hp, bit3 hn)
    float psum = 0.0f, nsum = 0.0f;
    int flags = 0;
    for (int j = tid; j < NB; j += 256) {
        float s = srow[j];
        bool same = (slab[j] == li);
        bool pos = same && (j != i);
        bool neg = !same;
        if (pos) {
            flags |= 1;
            if (s - C_MARGIN < nmax) { flags |= 4; psum += expf(-C_ALPHA * (s - C_BASE)); }
        }
        if (neg) {
            flags |= 2;
            if (s + C_MARGIN > pmin) { flags |= 8; nsum += expf(C_BETA * (s - C_BASE)); }
        }
    }
    rf[tid] = psum; ri[tid] = flags; __syncthreads();
    for (int o = 128; o > 0; o >>= 1) {
        if (tid < o) { rf[tid] += rf[tid + o]; ri[tid] |= ri[tid + o]; }
        __syncthreads();
    }
    float psum_all = rf[0];
    int   flags_all = ri[0];
    __syncthreads();
    rf[tid] = nsum; __syncthreads();
    for (int o = 128; o > 0; o >>= 1) {
        if (tid < o) rf[tid] += rf[tid + o];
        __syncthreads();
    }
    if (tid == 0) {
        float nsum_all = rf[0];
        bool valid = (flags_all & 15) == 15;
        float rl = log1pf(psum_all) / C_ALPHA + log1pf(nsum_all) / C_BETA;
        g_row_loss[i] = valid ? rl : 0.0f;
        g_valid[i]    = valid ? 1 : 0;
    }
}

// ---------------------------------------------------------------------------
// Kernel 3: deterministic final reduce -> scalar loss
// ---------------------------------------------------------------------------
__global__ __launch_bounds__(256) void final_kernel(float* __restrict__ out) {
    __shared__ float sf[256];
    __shared__ int   si[256];
    const int tid = threadIdx.x;
    float s = 0.0f; int n = 0;
    for (int j = tid; j < NB; j += 256) { s += g_row_loss[j]; n += g_valid[j]; }
    sf[tid] = s; si[tid] = n; __syncthreads();
    for (int o = 128; o > 0; o >>= 1) {
        if (tid < o) { sf[tid] += sf[tid + o]; si[tid] += si[tid + o]; }
        __syncthreads();
    }
    if (tid == 0) {
        int nv = si[0] > 1 ? si[0] : 1;
        out[0] = sf[0] / (float)nv;
    }
}

// ---------------------------------------------------------------------------
extern "C" void kernel_launch(void* const* d_in, const int* in_sizes, int n_in,
                              void* d_out, int out_size) {
    const float* E      = (const float*)d_in[0];
    const int*   labels = (const int*)d_in[1];
    float*       out    = (float*)d_out;

    cudaFuncSetAttribute(gemm_kernel, cudaFuncAttributeMaxDynamicSharedMemorySize,
                         ND * BM * 4 + ND * BN * 4);           // 128 KB
    cudaFuncSetAttribute(row_kernel, cudaFuncAttributeMaxDynamicSharedMemorySize,
                         NB * 4 + NB * 4);                     // 64 KB

    gemm_kernel<<<dim3(NB / BN, NB / BM), 256, ND * BM * 4 + ND * BN * 4>>>(E);
    row_kernel<<<NB, 256, NB * 4 + NB * 4>>>(labels);
    final_kernel<<<1, 256>>>(out);
}

// round 3
// speedup vs baseline: 2.6247x; 2.6247x over previous
#include <cuda_runtime.h>
#include <cuda_bf16.h>
#include <cstdint>
#include <math.h>

#define NB 8192
#define ND 128
#define C_ALPHA 2.0f
#define C_BETA 50.0f
#define C_BASE 0.5f
#define C_MARGIN 0.1f

// ---------------------------------------------------------------------------
// Scratch (allocation-free rule: __device__ globals)
// ---------------------------------------------------------------------------
__device__ float g_sim[(size_t)NB * NB];           // 256 MB
__device__ __nv_bfloat16 g_Ehi[(size_t)NB * ND];   // 2 MB
__device__ __nv_bfloat16 g_Elo[(size_t)NB * ND];   // 2 MB
__device__ float g_row_loss[NB];
__device__ int   g_valid[NB];

__device__ __forceinline__ uint32_t smem_u32(const void* p) {
    uint32_t a;
    asm("{ .reg .u64 t; cvta.to.shared.u64 t, %1; cvt.u32.u64 %0, t; }" : "=r"(a) : "l"(p));
    return a;
}

#define LDMATRIX_X4(r0, r1, r2, r3, addr)                                      \
    asm volatile("ldmatrix.sync.aligned.m8n8.x4.shared.b16 {%0,%1,%2,%3}, [%4];" \
                 : "=r"(r0), "=r"(r1), "=r"(r2), "=r"(r3) : "r"(addr))
#define LDMATRIX_X2(r0, r1, addr)                                              \
    asm volatile("ldmatrix.sync.aligned.m8n8.x2.shared.b16 {%0,%1}, [%2];"     \
                 : "=r"(r0), "=r"(r1) : "r"(addr))
#define MMA16816(c, a, b)                                                      \
    asm volatile("mma.sync.aligned.m16n8k16.row.col.f32.bf16.bf16.f32 "        \
                 "{%0,%1,%2,%3}, {%4,%5,%6,%7}, {%8,%9}, {%0,%1,%2,%3};"       \
                 : "+f"((c)[0]), "+f"((c)[1]), "+f"((c)[2]), "+f"((c)[3])      \
                 : "r"((a)[0]), "r"((a)[1]), "r"((a)[2]), "r"((a)[3]),         \
                   "r"((b)[0]), "r"((b)[1]))

// ---------------------------------------------------------------------------
// Kernel 0: split fp32 embeddings into bf16 hi + bf16 lo
// ---------------------------------------------------------------------------
__global__ __launch_bounds__(256) void split_kernel(const float* __restrict__ E) {
    int i = blockIdx.x * 256 + threadIdx.x;
    float x = E[i];
    __nv_bfloat16 h = __float2bfloat16(x);
    g_Ehi[i] = h;
    g_Elo[i] = __float2bfloat16(x - __bfloat162float(h));
}

// ---------------------------------------------------------------------------
// Kernel 1: sim = Ehi*Ehi^T + Ehi*Elo^T + Elo*Ehi^T via mma.sync (bf16->fp32)
// One CTA per 128x128 tile; 8 warps (2x4), 64x32 warp tiles; K=128 resident.
// ---------------------------------------------------------------------------
#define PAD 8
#define LDT (ND + PAD)                    // 136 bf16 per row
#define TILE_B (128 * LDT * 2)            // 34816 bytes per tile
#define OFF_AHI 0
#define OFF_ALO (OFF_AHI + TILE_B)
#define OFF_BHI (OFF_ALO + TILE_B)
#define OFF_BLO (OFF_BHI + TILE_B)
#define GEMM_SMEM (OFF_BLO + TILE_B)      // 139264 bytes

__global__ __launch_bounds__(256, 1) void gemm_mma_kernel() {
    extern __shared__ char smem[];
    const uint32_t sbase = smem_u32(smem);
    const int tid  = threadIdx.x;
    const int wid  = tid >> 5;
    const int lane = tid & 31;
    const int bm = blockIdx.y * 128;
    const int bn = blockIdx.x * 128;

    // ---- load 4 tiles (Ahi/Alo rows bm.., Bhi/Blo rows bn..), padded rows ----
    for (int t = tid; t < 2048; t += 256) {
        const int r = t >> 4;
        const int c = t & 15;
        const uint32_t so = (uint32_t)r * (LDT * 2) + c * 16;
        const size_t ga = (size_t)(bm + r) * ND + c * 8;
        const size_t gb = (size_t)(bn + r) * ND + c * 8;
        *(uint4*)(smem + OFF_AHI + so) = *(const uint4*)(g_Ehi + ga);
        *(uint4*)(smem + OFF_ALO + so) = *(const uint4*)(g_Elo + ga);
        *(uint4*)(smem + OFF_BHI + so) = *(const uint4*)(g_Ehi + gb);
        *(uint4*)(smem + OFF_BLO + so) = *(const uint4*)(g_Elo + gb);
    }
    __syncthreads();

    const int warp_m = wid >> 2;          // 0..1
    const int warp_n = wid & 3;           // 0..3
    const int mbase = warp_m * 64;
    const int nbase = warp_n * 32;

    // ldmatrix lane-address components
    const int arow = ((lane >> 3) & 1) * 8 + (lane & 7); // +8 for matrices 1,3
    const int acol = ((lane >> 4) & 1) * 8;              // +8 cols for matrices 2,3
    const int brow = lane & 7;
    const int bcol = ((lane >> 3) & 1) * 8;              // lanes 8-15 -> k+8

    float acc[4][4][4];
#pragma unroll
    for (int mi = 0; mi < 4; mi++)
#pragma unroll
        for (int ni = 0; ni < 4; ni++)
#pragma unroll
            for (int q = 0; q < 4; q++) acc[mi][ni][q] = 0.0f;

    const uint32_t Abases[3] = {sbase + OFF_AHI, sbase + OFF_AHI, sbase + OFF_ALO};
    const uint32_t Bbases[3] = {sbase + OFF_BHI, sbase + OFF_BLO, sbase + OFF_BHI};

#pragma unroll 1
    for (int p = 0; p < 3; p++) {
        const uint32_t Ab = Abases[p];
        const uint32_t Bb = Bbases[p];
#pragma unroll
        for (int k0 = 0; k0 < ND; k0 += 16) {
            uint32_t a[4][4], b[4][2];
#pragma unroll
            for (int mi = 0; mi < 4; mi++) {
                uint32_t ad = Ab + ((mbase + mi * 16 + arow) * LDT + k0 + acol) * 2;
                LDMATRIX_X4(a[mi][0], a[mi][1], a[mi][2], a[mi][3], ad);
            }
#pragma unroll
            for (int ni = 0; ni < 4; ni++) {
                uint32_t bd = Bb + ((nbase + ni * 8 + brow) * LDT + k0 + bcol) * 2;
                LDMATRIX_X2(b[ni][0], b[ni][1], bd);
            }
#pragma unroll
            for (int mi = 0; mi < 4; mi++)
#pragma unroll
                for (int ni = 0; ni < 4; ni++)
                    MMA16816(acc[mi][ni], a[mi], b[ni]);
        }
    }

    // ---- epilogue: fragment layout -> gmem (float2 stores) ----
    const int g   = lane >> 2;
    const int tig = lane & 3;
#pragma unroll
    for (int mi = 0; mi < 4; mi++) {
        const size_t row0 = (size_t)(bm + mbase + mi * 16 + g);
        const size_t row1 = row0 + 8;
#pragma unroll
        for (int ni = 0; ni < 4; ni++) {
            const int col = bn + nbase + ni * 8 + tig * 2;
            *(float2*)(g_sim + row0 * NB + col) = make_float2(acc[mi][ni][0], acc[mi][ni][1]);
            *(float2*)(g_sim + row1 * NB + col) = make_float2(acc[mi][ni][2], acc[mi][ni][3]);
        }
    }
}

// ---------------------------------------------------------------------------
// Kernel 2: per-row mining + loss (row staged in SMEM, two passes)
// ---------------------------------------------------------------------------
__global__ __launch_bounds__(256) void row_kernel(const int* __restrict__ labels) {
    extern __shared__ float sm[];
    float* srow = sm;                     // NB floats
    int*   slab = (int*)(sm + NB);        // NB ints
    __shared__ float rf[256];
    __shared__ int   ri[256];
    __shared__ float s_pmin, s_nmax;

    const int i   = blockIdx.x;
    const int tid = threadIdx.x;

    for (int t = tid; t < NB / 4; t += 256) {
        ((float4*)srow)[t] = ((const float4*)(g_sim + (size_t)i * NB))[t];
        ((int4*)slab)[t]   = ((const int4*)labels)[t];
    }
    __syncthreads();

    const int li = slab[i];

    float pmin = INFINITY, nmax = -INFINITY;
    for (int j = tid; j < NB; j += 256) {
        float s = srow[j];
        bool same = (slab[j] == li);
        if (same && j != i) pmin = fminf(pmin, s);
        if (!same)          nmax = fmaxf(nmax, s);
    }
    rf[tid] = pmin; __syncthreads();
    for (int o = 128; o > 0; o >>= 1) {
        if (tid < o) rf[tid] = fminf(rf[tid], rf[tid + o]);
        __syncthreads();
    }
    if (tid == 0) s_pmin = rf[0];
    __syncthreads();
    rf[tid] = nmax; __syncthreads();
    for (int o = 128; o > 0; o >>= 1) {
        if (tid < o) rf[tid] = fmaxf(rf[tid], rf[tid + o]);
        __syncthreads();
    }
    if (tid == 0) s_nmax = rf[0];
    __syncthreads();
    pmin = s_pmin;
    nmax = s_nmax;

    float psum = 0.0f, nsum = 0.0f;
    int flags = 0;
    for (int j = tid; j < NB; j += 256) {
        float s = srow[j];
        bool same = (slab[j] == li);
        bool pos = same && (j != i);
        bool neg = !same;
        if (pos) {
            flags |= 1;
            if (s - C_MARGIN < nmax) { flags |= 4; psum += __expf(-C_ALPHA * (s - C_BASE)); }
        }
        if (neg) {
            flags |= 2;
            if (s + C_MARGIN > pmin) { flags |= 8; nsum += __expf(C_BETA * (s - C_BASE)); }
        }
    }
    rf[tid] = psum; ri[tid] = flags; __syncthreads();
    for (int o = 128; o > 0; o >>= 1) {
        if (tid < o) { rf[tid] += rf[tid + o]; ri[tid] |= ri[tid + o]; }
        __syncthreads();
    }
    float psum_all = rf[0];
    int   flags_all = ri[0];
    __syncthreads();
    rf[tid] = nsum; __syncthreads();
    for (int o = 128; o > 0; o >>= 1) {
        if (tid < o) rf[tid] += rf[tid + o];
        __syncthreads();
    }
    if (tid == 0) {
        float nsum_all = rf[0];
        bool valid = (flags_all & 15) == 15;
        float rl = log1pf(psum_all) / C_ALPHA + log1pf(nsum_all) / C_BETA;
        g_row_loss[i] = valid ? rl : 0.0f;
        g_valid[i]    = valid ? 1 : 0;
    }
}

// ---------------------------------------------------------------------------
// Kernel 3: deterministic final reduce -> scalar
// ---------------------------------------------------------------------------
__global__ __launch_bounds__(256) void final_kernel(float* __restrict__ out) {
    __shared__ float sf[256];
    __shared__ int   si[256];
    const int tid = threadIdx.x;
    float s = 0.0f; int n = 0;
    for (int j = tid; j < NB; j += 256) { s += g_row_loss[j]; n += g_valid[j]; }
    sf[tid] = s; si[tid] = n; __syncthreads();
    for (int o = 128; o > 0; o >>= 1) {
        if (tid < o) { sf[tid] += sf[tid + o]; si[tid] += si[tid + o]; }
        __syncthreads();
    }
    if (tid == 0) {
        int nv = si[0] > 1 ? si[0] : 1;
        out[0] = sf[0] / (float)nv;
    }
}

// ---------------------------------------------------------------------------
extern "C" void kernel_launch(void* const* d_in, const int* in_sizes, int n_in,
                              void* d_out, int out_size) {
    const float* E      = (const float*)d_in[0];
    const int*   labels = (const int*)d_in[1];
    float*       out    = (float*)d_out;

    cudaFuncSetAttribute(gemm_mma_kernel, cudaFuncAttributeMaxDynamicSharedMemorySize,
                         GEMM_SMEM);
    cudaFuncSetAttribute(row_kernel, cudaFuncAttributeMaxDynamicSharedMemorySize,
                         NB * 4 + NB * 4);

    split_kernel<<<NB * ND / 256, 256>>>(E);
    gemm_mma_kernel<<<dim3(NB / 128, NB / 128), 256, GEMM_SMEM>>>();
    row_kernel<<<NB, 256, NB * 4 + NB * 4>>>(labels);
    final_kernel<<<1, 256>>>(out);
}

// round 4
// speedup vs baseline: 3.3759x; 1.2862x over previous
#include <cuda_runtime.h>
#include <cuda_bf16.h>
#include <cstdint>
#include <math.h>

#define NB 8192
#define ND 128
#define C_ALPHA 2.0f
#define C_BETA 50.0f
#define C_BASE 0.5f
#define C_MARGIN 0.1f

// ---------------------------------------------------------------------------
// Scratch (allocation-free rule: __device__ globals)
// ---------------------------------------------------------------------------
__device__ float g_sim[(size_t)NB * NB];           // 256 MB
__device__ __nv_bfloat16 g_Ehi[(size_t)NB * ND];   // 2 MB
__device__ __nv_bfloat16 g_Elo[(size_t)NB * ND];   // 2 MB
__device__ float g_loss_sum;
__device__ int   g_valid_cnt;

__device__ __forceinline__ uint32_t smem_u32(const void* p) {
    uint32_t a;
    asm("{ .reg .u64 t; cvta.to.shared.u64 t, %1; cvt.u32.u64 %0, t; }" : "=r"(a) : "l"(p));
    return a;
}

#define LDMATRIX_X4(r0, r1, r2, r3, addr)                                      \
    asm volatile("ldmatrix.sync.aligned.m8n8.x4.shared.b16 {%0,%1,%2,%3}, [%4];" \
                 : "=r"(r0), "=r"(r1), "=r"(r2), "=r"(r3) : "r"(addr))
#define LDMATRIX_X2(r0, r1, addr)                                              \
    asm volatile("ldmatrix.sync.aligned.m8n8.x2.shared.b16 {%0,%1}, [%2];"     \
                 : "=r"(r0), "=r"(r1) : "r"(addr))
#define MMA16816(c, a, b)                                                      \
    asm volatile("mma.sync.aligned.m16n8k16.row.col.f32.bf16.bf16.f32 "        \
                 "{%0,%1,%2,%3}, {%4,%5,%6,%7}, {%8,%9}, {%0,%1,%2,%3};"       \
                 : "+f"((c)[0]), "+f"((c)[1]), "+f"((c)[2]), "+f"((c)[3])      \
                 : "r"((a)[0]), "r"((a)[1]), "r"((a)[2]), "r"((a)[3]),         \
                   "r"((b)[0]), "r"((b)[1]))

// ---------------------------------------------------------------------------
// Kernel 0: split fp32 embeddings into bf16 hi + bf16 lo (+ zero accumulators)
// ---------------------------------------------------------------------------
__global__ __launch_bounds__(256) void split_kernel(const float* __restrict__ E) {
    int i = blockIdx.x * 256 + threadIdx.x;
    if (i == 0) { g_loss_sum = 0.0f; g_valid_cnt = 0; }
    float x = E[i];
    __nv_bfloat16 h = __float2bfloat16(x);
    g_Ehi[i] = h;
    g_Elo[i] = __float2bfloat16(x - __bfloat162float(h));
}

// ---------------------------------------------------------------------------
// Kernel 1: sim = Ehi*Ehi^T + Ehi*Elo^T + Elo*Ehi^T via mma.sync (bf16->fp32)
// Upper-triangular tiles only (sim symmetric): bx >= by. Off-diagonal tiles
// store both the direct tile and its transpose (staged through SMEM).
// ---------------------------------------------------------------------------
#define PAD 8
#define LDT (ND + PAD)                    // 136 bf16 per row
#define TILE_B (128 * LDT * 2)            // 34816 bytes per tile
#define OFF_AHI 0
#define OFF_ALO (OFF_AHI + TILE_B)
#define OFF_BHI (OFF_ALO + TILE_B)
#define OFF_BLO (OFF_BHI + TILE_B)
#define GEMM_SMEM (OFF_BLO + TILE_B)      // 139264 bytes
#define TLD 132                           // fp32 transpose-stage row stride

__global__ __launch_bounds__(256, 1) void gemm_mma_kernel() {
    if (blockIdx.x < blockIdx.y) return;  // symmetry: only bx >= by
    extern __shared__ char smem[];
    const uint32_t sbase = smem_u32(smem);
    const int tid  = threadIdx.x;
    const int wid  = tid >> 5;
    const int lane = tid & 31;
    const int bm = blockIdx.y * 128;
    const int bn = blockIdx.x * 128;
    const bool diag = (bm == bn);

    // ---- load tiles (Ahi/Alo rows bm.., Bhi/Blo rows bn..), padded rows ----
    for (int t = tid; t < 2048; t += 256) {
        const int r = t >> 4;
        const int c = t & 15;
        const uint32_t so = (uint32_t)r * (LDT * 2) + c * 16;
        const size_t ga = (size_t)(bm + r) * ND + c * 8;
        *(uint4*)(smem + OFF_AHI + so) = *(const uint4*)(g_Ehi + ga);
        *(uint4*)(smem + OFF_ALO + so) = *(const uint4*)(g_Elo + ga);
        if (!diag) {
            const size_t gb = (size_t)(bn + r) * ND + c * 8;
            *(uint4*)(smem + OFF_BHI + so) = *(const uint4*)(g_Ehi + gb);
            *(uint4*)(smem + OFF_BLO + so) = *(const uint4*)(g_Elo + gb);
        }
    }
    __syncthreads();

    const int warp_m = wid >> 2;
    const int warp_n = wid & 3;
    const int mbase = warp_m * 64;
    const int nbase = warp_n * 32;

    const int arow = ((lane >> 3) & 1) * 8 + (lane & 7);
    const int acol = ((lane >> 4) & 1) * 8;
    const int brow = lane & 7;
    const int bcol = ((lane >> 3) & 1) * 8;

    float acc[4][4][4];
#pragma unroll
    for (int mi = 0; mi < 4; mi++)
#pragma unroll
        for (int ni = 0; ni < 4; ni++)
#pragma unroll
            for (int q = 0; q < 4; q++) acc[mi][ni][q] = 0.0f;

    const uint32_t bh = diag ? OFF_AHI : OFF_BHI;
    const uint32_t bl = diag ? OFF_ALO : OFF_BLO;
    const uint32_t Abases[3] = {sbase + OFF_AHI, sbase + OFF_AHI, sbase + OFF_ALO};
    const uint32_t Bbases[3] = {sbase + bh, sbase + bl, sbase + bh};

#pragma unroll 1
    for (int p = 0; p < 3; p++) {
        const uint32_t Ab = Abases[p];
        const uint32_t Bb = Bbases[p];
#pragma unroll
        for (int k0 = 0; k0 < ND; k0 += 16) {
            uint32_t a[4][4], b[4][2];
#pragma unroll
            for (int mi = 0; mi < 4; mi++) {
                uint32_t ad = Ab + ((mbase + mi * 16 + arow) * LDT + k0 + acol) * 2;
                LDMATRIX_X4(a[mi][0], a[mi][1], a[mi][2], a[mi][3], ad);
            }
#pragma unroll
            for (int ni = 0; ni < 4; ni++) {
                uint32_t bd = Bb + ((nbase + ni * 8 + brow) * LDT + k0 + bcol) * 2;
                LDMATRIX_X2(b[ni][0], b[ni][1], bd);
            }
#pragma unroll
            for (int mi = 0; mi < 4; mi++)
#pragma unroll
                for (int ni = 0; ni < 4; ni++)
                    MMA16816(acc[mi][ni], a[mi], b[ni]);
        }
    }

    // ---- direct store ----
    const int g   = lane >> 2;
    const int tig = lane & 3;
#pragma unroll
    for (int mi = 0; mi < 4; mi++) {
        const size_t row0 = (size_t)(bm + mbase + mi * 16 + g);
        const size_t row1 = row0 + 8;
#pragma unroll
        for (int ni = 0; ni < 4; ni++) {
            const int col = bn + nbase + ni * 8 + tig * 2;
            *(float2*)(g_sim + row0 * NB + col) = make_float2(acc[mi][ni][0], acc[mi][ni][1]);
            *(float2*)(g_sim + row1 * NB + col) = make_float2(acc[mi][ni][2], acc[mi][ni][3]);
        }
    }

    // ---- transposed store for off-diagonal tiles (stage via SMEM) ----
    if (!diag) {
        __syncthreads();               // all ldmatrix reads done; reuse smem
        float* st = (float*)smem;      // [128][TLD]
#pragma unroll
        for (int mi = 0; mi < 4; mi++) {
            const int r0 = mbase + mi * 16 + g;
#pragma unroll
            for (int ni = 0; ni < 4; ni++) {
                const int c0 = nbase + ni * 8 + tig * 2;
                st[(c0 + 0) * TLD + r0]     = acc[mi][ni][0];
                st[(c0 + 1) * TLD + r0]     = acc[mi][ni][1];
                st[(c0 + 0) * TLD + r0 + 8] = acc[mi][ni][2];
                st[(c0 + 1) * TLD + r0 + 8] = acc[mi][ni][3];
            }
        }
        __syncthreads();
        for (int t = tid; t < 128 * 32; t += 256) {
            const int r  = t >> 5;
            const int c4 = (t & 31) * 4;
            float4 v = *(float4*)(st + r * TLD + c4);
            *(float4*)(g_sim + (size_t)(bn + r) * NB + bm + c4) = v;
        }
    }
}

// ---------------------------------------------------------------------------
// Block reductions (warp shuffle + one smem round)
// ---------------------------------------------------------------------------
__device__ __forceinline__ float blk_red_min(float v, float* buf, int tid) {
#pragma unroll
    for (int o = 16; o > 0; o >>= 1) v = fminf(v, __shfl_xor_sync(0xFFFFFFFFu, v, o));
    if ((tid & 31) == 0) buf[tid >> 5] = v;
    __syncthreads();
    v = fminf(fminf(buf[0], buf[1]), fminf(buf[2], buf[3]));
    v = fminf(v, fminf(fminf(buf[4], buf[5]), fminf(buf[6], buf[7])));
    __syncthreads();
    return v;
}
__device__ __forceinline__ float blk_red_max(float v, float* buf, int tid) {
#pragma unroll
    for (int o = 16; o > 0; o >>= 1) v = fmaxf(v, __shfl_xor_sync(0xFFFFFFFFu, v, o));
    if ((tid & 31) == 0) buf[tid >> 5] = v;
    __syncthreads();
    v = fmaxf(fmaxf(buf[0], buf[1]), fmaxf(buf[2], buf[3]));
    v = fmaxf(v, fmaxf(fmaxf(buf[4], buf[5]), fmaxf(buf[6], buf[7])));
    __syncthreads();
    return v;
}
__device__ __forceinline__ float blk_red_sum(float v, float* buf, int tid) {
#pragma unroll
    for (int o = 16; o > 0; o >>= 1) v += __shfl_xor_sync(0xFFFFFFFFu, v, o);
    if ((tid & 31) == 0) buf[tid >> 5] = v;
    __syncthreads();
    v = (buf[0] + buf[1]) + (buf[2] + buf[3]) + (buf[4] + buf[5]) + (buf[6] + buf[7]);
    __syncthreads();
    return v;
}
__device__ __forceinline__ int blk_red_or(int v, int* buf, int tid) {
#pragma unroll
    for (int o = 16; o > 0; o >>= 1) v |= __shfl_xor_sync(0xFFFFFFFFu, v, o);
    if ((tid & 31) == 0) buf[tid >> 5] = v;
    __syncthreads();
    v = buf[0] | buf[1] | buf[2] | buf[3] | buf[4] | buf[5] | buf[6] | buf[7];
    __syncthreads();
    return v;
}

// ---------------------------------------------------------------------------
// Kernel 2: per-row mining + loss (row staged in SMEM, two passes, float4)
// ---------------------------------------------------------------------------
__global__ __launch_bounds__(256) void row_kernel(const int* __restrict__ labels) {
    extern __shared__ float sm[];
    float* srow = sm;                     // NB floats
    int*   slab = (int*)(sm + NB);        // NB ints
    __shared__ float rbuf[8];
    __shared__ int   ibuf[8];

    const int i   = blockIdx.x;
    const int tid = threadIdx.x;

    for (int t = tid; t < NB / 4; t += 256) {
        ((float4*)srow)[t] = ((const float4*)(g_sim + (size_t)i * NB))[t];
        ((int4*)slab)[t]   = ((const int4*)labels)[t];
    }
    __syncthreads();

    const int li = slab[i];

    // Pass 1: extrema
    float pmin = INFINITY, nmax = -INFINITY;
    for (int j4 = tid; j4 < NB / 4; j4 += 256) {
        float4 s = ((const float4*)srow)[j4];
        int4   L = ((const int4*)slab)[j4];
        const int j = j4 * 4;
        if (L.x == li) { if (j + 0 != i) pmin = fminf(pmin, s.x); } else nmax = fmaxf(nmax, s.x);
        if (L.y == li) { if (j + 1 != i) pmin = fminf(pmin, s.y); } else nmax = fmaxf(nmax, s.y);
        if (L.z == li) { if (j + 2 != i) pmin = fminf(pmin, s.z); } else nmax = fmaxf(nmax, s.z);
        if (L.w == li) { if (j + 3 != i) pmin = fminf(pmin, s.w); } else nmax = fmaxf(nmax, s.w);
    }
    pmin = blk_red_min(pmin, rbuf, tid);
    nmax = blk_red_max(nmax, rbuf, tid);

    // Pass 2: hard-pair sums + existence flags
    const float nthr = nmax - 0.45f;   // exp(beta*(s-nmax)) < e^-22.5 below this
    float psum = 0.0f, nsum = 0.0f;
    int flags = 0;
    for (int j4 = tid; j4 < NB / 4; j4 += 256) {
        float4 sv = ((const float4*)srow)[j4];
        int4   L  = ((const int4*)slab)[j4];
        const int j = j4 * 4;
        const float se[4] = {sv.x, sv.y, sv.z, sv.w};
        const int   le[4] = {L.x, L.y, L.z, L.w};
#pragma unroll
        for (int q = 0; q < 4; q++) {
            const float s = se[q];
            if (le[q] == li) {
                if (j + q != i) {
                    flags |= 1;
                    if (s - C_MARGIN < nmax) { flags |= 4; psum += __expf(-C_ALPHA * (s - C_BASE)); }
                }
            } else {
                flags |= 2;
                if (s + C_MARGIN > pmin) {
                    flags |= 8;
                    if (s > nthr) nsum += __expf(C_BETA * (s - C_BASE));
                }
            }
        }
    }
    psum  = blk_red_sum(psum, rbuf, tid);
    nsum  = blk_red_sum(nsum, rbuf, tid);
    flags = blk_red_or(flags, ibuf, tid);

    if (tid == 0) {
        const bool valid = (flags & 15) == 15;
        if (valid) {
            const float rl = log1pf(psum) / C_ALPHA + log1pf(nsum) / C_BETA;
            atomicAdd(&g_loss_sum, rl);
            atomicAdd(&g_valid_cnt, 1);
        }
    }
}

// ---------------------------------------------------------------------------
// Kernel 3: finalize
// ---------------------------------------------------------------------------
__global__ void final_kernel(float* __restrict__ out) {
    const int nv = g_valid_cnt > 1 ? g_valid_cnt : 1;
    out[0] = g_loss_sum / (float)nv;
}

// ---------------------------------------------------------------------------
extern "C" void kernel_launch(void* const* d_in, const int* in_sizes, int n_in,
                              void* d_out, int out_size) {
    const float* E      = (const float*)d_in[0];
    const int*   labels = (const int*)d_in[1];
    float*       out    = (float*)d_out;

    cudaFuncSetAttribute(gemm_mma_kernel, cudaFuncAttributeMaxDynamicSharedMemorySize,
                         GEMM_SMEM);
    cudaFuncSetAttribute(row_kernel, cudaFuncAttributeMaxDynamicSharedMemorySize,
                         NB * 4 + NB * 4);

    split_kernel<<<NB * ND / 256, 256>>>(E);
    gemm_mma_kernel<<<dim3(NB / 128, NB / 128), 256, GEMM_SMEM>>>();
    row_kernel<<<NB, 256, NB * 4 + NB * 4>>>(labels);
    final_kernel<<<1, 1>>>(out);
}

// round 5
// speedup vs baseline: 4.2708x; 1.2651x over previous
#include <cuda_runtime.h>
#include <cuda_bf16.h>
#include <cstdint>
#include <math.h>

#define NB 8192
#define ND 128
#define C_ALPHA 2.0f
#define C_BETA 50.0f
#define C_BASE 0.5f
#define C_MARGIN 0.1f

// ---------------------------------------------------------------------------
// Scratch (allocation-free rule: __device__ globals)
// ---------------------------------------------------------------------------
__device__ float g_sim[(size_t)NB * NB];           // 256 MB
__device__ __nv_bfloat16 g_Ehi[(size_t)NB * ND];   // 2 MB
__device__ __nv_bfloat16 g_Elo[(size_t)NB * ND];   // 2 MB
__device__ float g_loss_sum;
__device__ int   g_valid_cnt;

__device__ __forceinline__ uint32_t smem_u32(const void* p) {
    uint32_t a;
    asm("{ .reg .u64 t; cvta.to.shared.u64 t, %1; cvt.u32.u64 %0, t; }" : "=r"(a) : "l"(p));
    return a;
}

#define LDMATRIX_X4(r0, r1, r2, r3, addr)                                      \
    asm volatile("ldmatrix.sync.aligned.m8n8.x4.shared.b16 {%0,%1,%2,%3}, [%4];" \
                 : "=r"(r0), "=r"(r1), "=r"(r2), "=r"(r3) : "r"(addr))
#define LDMATRIX_X2(r0, r1, addr)                                              \
    asm volatile("ldmatrix.sync.aligned.m8n8.x2.shared.b16 {%0,%1}, [%2];"     \
                 : "=r"(r0), "=r"(r1) : "r"(addr))
#define MMA16816(c, a, b)                                                      \
    asm volatile("mma.sync.aligned.m16n8k16.row.col.f32.bf16.bf16.f32 "        \
                 "{%0,%1,%2,%3}, {%4,%5,%6,%7}, {%8,%9}, {%0,%1,%2,%3};"       \
                 : "+f"((c)[0]), "+f"((c)[1]), "+f"((c)[2]), "+f"((c)[3])      \
                 : "r"((a)[0]), "r"((a)[1]), "r"((a)[2]), "r"((a)[3]),         \
                   "r"((b)[0]), "r"((b)[1]))

// ---------------------------------------------------------------------------
// Kernel 0: split fp32 embeddings into bf16 hi + bf16 lo (+ zero accumulators)
// ---------------------------------------------------------------------------
__global__ __launch_bounds__(256) void split_kernel(const float* __restrict__ E) {
    int i = blockIdx.x * 256 + threadIdx.x;
    if (i == 0) { g_loss_sum = 0.0f; g_valid_cnt = 0; }
    float x = E[i];
    __nv_bfloat16 h = __float2bfloat16(x);
    g_Ehi[i] = h;
    g_Elo[i] = __float2bfloat16(x - __bfloat162float(h));
}

// ---------------------------------------------------------------------------
// Kernel 1: sim = Ehi*Ehi^T + Ehi*Elo^T + Elo*Ehi^T via mma.sync (bf16->fp32)
// Triangular 1-D grid (2080 tiles, bx >= by). Off-diagonal tiles also store
// the transposed tile (staged via SMEM).
// ---------------------------------------------------------------------------
#define PAD 8
#define LDT (ND + PAD)                    // 136 bf16 per row
#define TILE_B (128 * LDT * 2)            // 34816 bytes per tile
#define OFF_AHI 0
#define OFF_ALO (OFF_AHI + TILE_B)
#define OFF_BHI (OFF_ALO + TILE_B)
#define OFF_BLO (OFF_BHI + TILE_B)
#define GEMM_SMEM (OFF_BLO + TILE_B)      // 139264 bytes
#define TLD 132                           // fp32 transpose-stage row stride
#define NTILE (NB / 128)                  // 64
#define NTRI (NTILE * (NTILE + 1) / 2)    // 2080

__global__ __launch_bounds__(256, 1) void gemm_mma_kernel() {
    // decode linear triangle index -> (by, bx), bx >= by
    int rem = blockIdx.x;
    int by = 0;
    while (rem >= NTILE - by) { rem -= NTILE - by; by++; }
    const int bx = by + rem;

    extern __shared__ char smem[];
    const uint32_t sbase = smem_u32(smem);
    const int tid  = threadIdx.x;
    const int wid  = tid >> 5;
    const int lane = tid & 31;
    const int bm = by * 128;
    const int bn = bx * 128;
    const bool diag = (bm == bn);

    for (int t = tid; t < 2048; t += 256) {
        const int r = t >> 4;
        const int c = t & 15;
        const uint32_t so = (uint32_t)r * (LDT * 2) + c * 16;
        const size_t ga = (size_t)(bm + r) * ND + c * 8;
        *(uint4*)(smem + OFF_AHI + so) = *(const uint4*)(g_Ehi + ga);
        *(uint4*)(smem + OFF_ALO + so) = *(const uint4*)(g_Elo + ga);
        if (!diag) {
            const size_t gb = (size_t)(bn + r) * ND + c * 8;
            *(uint4*)(smem + OFF_BHI + so) = *(const uint4*)(g_Ehi + gb);
            *(uint4*)(smem + OFF_BLO + so) = *(const uint4*)(g_Elo + gb);
        }
    }
    __syncthreads();

    const int warp_m = wid >> 2;
    const int warp_n = wid & 3;
    const int mbase = warp_m * 64;
    const int nbase = warp_n * 32;

    const int arow = ((lane >> 3) & 1) * 8 + (lane & 7);
    const int acol = ((lane >> 4) & 1) * 8;
    const int brow = lane & 7;
    const int bcol = ((lane >> 3) & 1) * 8;

    float acc[4][4][4];
#pragma unroll
    for (int mi = 0; mi < 4; mi++)
#pragma unroll
        for (int ni = 0; ni < 4; ni++)
#pragma unroll
            for (int q = 0; q < 4; q++) acc[mi][ni][q] = 0.0f;

    const uint32_t bh = diag ? OFF_AHI : OFF_BHI;
    const uint32_t bl = diag ? OFF_ALO : OFF_BLO;
    const uint32_t Abases[3] = {sbase + OFF_AHI, sbase + OFF_AHI, sbase + OFF_ALO};
    const uint32_t Bbases[3] = {sbase + bh, sbase + bl, sbase + bh};

#pragma unroll 1
    for (int p = 0; p < 3; p++) {
        const uint32_t Ab = Abases[p];
        const uint32_t Bb = Bbases[p];
#pragma unroll
        for (int k0 = 0; k0 < ND; k0 += 16) {
            uint32_t a[4][4], b[4][2];
#pragma unroll
            for (int mi = 0; mi < 4; mi++) {
                uint32_t ad = Ab + ((mbase + mi * 16 + arow) * LDT + k0 + acol) * 2;
                LDMATRIX_X4(a[mi][0], a[mi][1], a[mi][2], a[mi][3], ad);
            }
#pragma unroll
            for (int ni = 0; ni < 4; ni++) {
                uint32_t bd = Bb + ((nbase + ni * 8 + brow) * LDT + k0 + bcol) * 2;
                LDMATRIX_X2(b[ni][0], b[ni][1], bd);
            }
#pragma unroll
            for (int mi = 0; mi < 4; mi++)
#pragma unroll
                for (int ni = 0; ni < 4; ni++)
                    MMA16816(acc[mi][ni], a[mi], b[ni]);
        }
    }

    // ---- direct store ----
    const int g   = lane >> 2;
    const int tig = lane & 3;
#pragma unroll
    for (int mi = 0; mi < 4; mi++) {
        const size_t row0 = (size_t)(bm + mbase + mi * 16 + g);
        const size_t row1 = row0 + 8;
#pragma unroll
        for (int ni = 0; ni < 4; ni++) {
            const int col = bn + nbase + ni * 8 + tig * 2;
            *(float2*)(g_sim + row0 * NB + col) = make_float2(acc[mi][ni][0], acc[mi][ni][1]);
            *(float2*)(g_sim + row1 * NB + col) = make_float2(acc[mi][ni][2], acc[mi][ni][3]);
        }
    }

    // ---- transposed store for off-diagonal tiles (stage via SMEM) ----
    if (!diag) {
        __syncthreads();
        float* st = (float*)smem;      // [128][TLD]
#pragma unroll
        for (int mi = 0; mi < 4; mi++) {
            const int r0 = mbase + mi * 16 + g;
#pragma unroll
            for (int ni = 0; ni < 4; ni++) {
                const int c0 = nbase + ni * 8 + tig * 2;
                st[(c0 + 0) * TLD + r0]     = acc[mi][ni][0];
                st[(c0 + 1) * TLD + r0]     = acc[mi][ni][1];
                st[(c0 + 0) * TLD + r0 + 8] = acc[mi][ni][2];
                st[(c0 + 1) * TLD + r0 + 8] = acc[mi][ni][3];
            }
        }
        __syncthreads();
        for (int t = tid; t < 128 * 32; t += 256) {
            const int r  = t >> 5;
            const int c4 = (t & 31) * 4;
            float4 v = *(float4*)(st + r * TLD + c4);
            *(float4*)(g_sim + (size_t)(bn + r) * NB + bm + c4) = v;
        }
    }
}

// ---------------------------------------------------------------------------
// Kernel 2: per-row mining + loss. 512 threads, 8 rows per CTA.
// Row data + labels live in REGISTERS (16 elems/thread); labels loaded once.
// validity: anyPos <=> pmin<inf, anyNeg <=> nmax>-inf, hardPos <=> psum>0,
// hardNeg <=> nsum>0 (the nmax element is hard & never cut off when any is).
// ---------------------------------------------------------------------------
#define RK_ROWS 8

__global__ __launch_bounds__(512, 2) void row_kernel(const int* __restrict__ labels) {
    __shared__ float bufA[16], bufB[16];
    __shared__ float s_a, s_b;

    const int tid  = threadIdx.x;
    const int lane = tid & 31;
    const int wid  = tid >> 5;

    int4 lab[4];
#pragma unroll
    for (int q = 0; q < 4; q++) lab[q] = ((const int4*)labels)[q * 512 + tid];

    for (int r = 0; r < RK_ROWS; r++) {
        const int i  = blockIdx.x * RK_ROWS + r;
        const int li = __ldg(labels + i);

        float4 sv[4];
        const float4* row4 = (const float4*)(g_sim + (size_t)i * NB);
#pragma unroll
        for (int q = 0; q < 4; q++) sv[q] = row4[q * 512 + tid];

        // ---- pass 1: extrema ----
        float pmin = INFINITY, nmax = -INFINITY;
#pragma unroll
        for (int q = 0; q < 4; q++) {
            const int j0 = (q * 512 + tid) * 4;
            const float s[4] = {sv[q].x, sv[q].y, sv[q].z, sv[q].w};
            const int   l[4] = {lab[q].x, lab[q].y, lab[q].z, lab[q].w};
#pragma unroll
            for (int e = 0; e < 4; e++) {
                if (l[e] == li) { if (j0 + e != i) pmin = fminf(pmin, s[e]); }
                else nmax = fmaxf(nmax, s[e]);
            }
        }
#pragma unroll
        for (int o = 16; o; o >>= 1) {
            pmin = fminf(pmin, __shfl_xor_sync(0xFFFFFFFFu, pmin, o));
            nmax = fmaxf(nmax, __shfl_xor_sync(0xFFFFFFFFu, nmax, o));
        }
        if (lane == 0) { bufA[wid] = pmin; bufB[wid] = nmax; }
        __syncthreads();
        if (tid == 0) {
            float a = bufA[0], m = bufB[0];
#pragma unroll
            for (int k = 1; k < 16; k++) { a = fminf(a, bufA[k]); m = fmaxf(m, bufB[k]); }
            s_a = a; s_b = m;
        }
        __syncthreads();
        pmin = s_a;
        nmax = s_b;
        __syncthreads();   // protect bufA/bufB before pass-2 writes

        // ---- pass 2: hard-pair sums ----
        const float nthr = nmax - 0.45f;   // skipped terms < e^-22.5 * max term
        float psum = 0.0f, nsum = 0.0f;
#pragma unroll
        for (int q = 0; q < 4; q++) {
            const int j0 = (q * 512 + tid) * 4;
            const float s[4] = {sv[q].x, sv[q].y, sv[q].z, sv[q].w};
            const int   l[4] = {lab[q].x, lab[q].y, lab[q].z, lab[q].w};
#pragma unroll
            for (int e = 0; e < 4; e++) {
                const float sj = s[e];
                if (l[e] == li) {
                    if (j0 + e != i && sj - C_MARGIN < nmax)
                        psum += __expf(-C_ALPHA * (sj - C_BASE));
                } else {
                    if (sj + C_MARGIN > pmin && sj > nthr)
                        nsum += __expf(C_BETA * (sj - C_BASE));
                }
            }
        }
#pragma unroll
        for (int o = 16; o; o >>= 1) {
            psum += __shfl_xor_sync(0xFFFFFFFFu, psum, o);
            nsum += __shfl_xor_sync(0xFFFFFFFFu, nsum, o);
        }
        if (lane == 0) { bufA[wid] = psum; bufB[wid] = nsum; }
        __syncthreads();
        if (tid == 0) {
            float ps = 0.0f, ns = 0.0f;
#pragma unroll
            for (int k = 0; k < 16; k++) { ps += bufA[k]; ns += bufB[k]; }
            const bool valid = (pmin < INFINITY) && (nmax > -INFINITY) &&
                               (ps > 0.0f) && (ns > 0.0f);
            if (valid) {
                atomicAdd(&g_loss_sum, log1pf(ps) / C_ALPHA + log1pf(ns) / C_BETA);
                atomicAdd(&g_valid_cnt, 1);
            }
        }
        __syncthreads();   // bufs consumed before next row overwrites
    }
}

// ---------------------------------------------------------------------------
// Kernel 3: finalize
// ---------------------------------------------------------------------------
__global__ void final_kernel(float* __restrict__ out) {
    const int nv = g_valid_cnt > 1 ? g_valid_cnt : 1;
    out[0] = g_loss_sum / (float)nv;
}

// ---------------------------------------------------------------------------
extern "C" void kernel_launch(void* const* d_in, const int* in_sizes, int n_in,
                              void* d_out, int out_size) {
    const float* E      = (const float*)d_in[0];
    const int*   labels = (const int*)d_in[1];
    float*       out    = (float*)d_out;

    cudaFuncSetAttribute(gemm_mma_kernel, cudaFuncAttributeMaxDynamicSharedMemorySize,
                         GEMM_SMEM);

    split_kernel<<<NB * ND / 256, 256>>>(E);
    gemm_mma_kernel<<<NTRI, 256, GEMM_SMEM>>>();
    row_kernel<<<NB / RK_ROWS, 512>>>(labels);
    final_kernel<<<1, 1>>>(out);
}